// round 6
// baseline (speedup 1.0000x reference)
#include <cuda_runtime.h>
#include <cstdint>

#define NATOMS 6144
#define FDIM   128
#define HDIM   64
#define NMOL   48
#define NBLK   148     // co-resident on B300(148)/GB300(152)
#define NTHR   1024
#define NWARP  32
#define ASLOT  48      // padded atom slots per block (acnt is 41..42)

// Device-global scratch. All writes are deterministic overwrites (replay-safe).
__device__ float4 g_A[NATOMS];        // pos.xyz, q_raw
__device__ float4 g_B[NATOMS];        // mu.xyz, sqrt(softplus(c6))
__device__ int    g_segs[NMOL];
__device__ int    g_sege[NMOL];
__device__ double g_partial[NBLK];
__device__ volatile int g_sense;
__device__ int    g_count;
__device__ int    g_done;

__device__ __forceinline__ void grid_barrier() {
    __syncthreads();
    if (threadIdx.x == 0) {
        int s = g_sense;
        __threadfence();
        if (atomicAdd(&g_count, 1) == NBLK - 1) {
            g_count = 0;
            __threadfence();
            g_sense = s ^ 1;
        } else {
            while (g_sense == s) { }
        }
    }
    __syncthreads();
    __threadfence();
}

// ---- f32x2 packed-FMA helpers (FFMA2 on sm_100+) ---------------------------
__device__ __forceinline__ long long dupf(float w) {
    long long d; unsigned r = __float_as_uint(w);
    asm("mov.b64 %0, {%1, %1};" : "=l"(d) : "r"(r));
    return d;
}
__device__ __forceinline__ void ffma2(long long& a, long long h, long long w) {
    asm("fma.rn.f32x2 %0, %1, %2, %0;" : "+l"(a) : "l"(h), "l"(w));
}
__device__ __forceinline__ void unpack2(long long a, float& lo, float& hi) {
    unsigned l, h;
    asm("mov.b64 {%0, %1}, %2;" : "=r"(l), "=r"(h) : "l"(a));
    lo = __uint_as_float(l); hi = __uint_as_float(h);
}

__device__ __forceinline__ void tma_bulk_1d(uint32_t dst, const void* src,
                                            uint32_t bytes, uint32_t mbar) {
    asm volatile(
        "cp.async.bulk.shared::cta.global.mbarrier::complete_tx::bytes [%0], [%1], %2, [%3];"
        :: "r"(dst), "l"(src), "r"(bytes), "r"(mbar) : "memory");
}

extern "C" __global__ void __launch_bounds__(NTHR, 1) fused_kernel(
    const float* __restrict__ h0, const float* __restrict__ h1,
    const float* __restrict__ pos, const int* __restrict__ batch,
    const float* __restrict__ qW1, const float* __restrict__ qb1,
    const float* __restrict__ qW2, const float* __restrict__ qb2,
    const float* __restrict__ cW1, const float* __restrict__ cb1,
    const float* __restrict__ cW2, const float* __restrict__ cb2,
    const float* __restrict__ muW, float* __restrict__ out)
{
    extern __shared__ float smem[];
    float* sH0  = smem;                        // 48*128 floats (TMA dst; later overlaid)
    float* sWq  = smem + ASLOT * FDIM;         // 128*64 (TMA dst)
    float* sWc  = sWq + FDIM * HDIM;           // 128*64 (TMA dst)
    float* sH0P = sWc + FDIM * HDIM;           // pair-major acts
    long long* sComb = (long long*)sH0;        // overlay: MLP f-half partials (24 KB)

    __shared__ float  sPQ[4][2][12];
    __shared__ float  sPC[4][2][12];
    __shared__ float  s_mu[ASLOT][3];
    __shared__ float  s_qmean[NMOL];
    __shared__ double sDD[NWARP];
    __shared__ int    s_last;
    __shared__ __align__(8) unsigned long long mbar[1];

    const int tid  = threadIdx.x;
    const int bid  = blockIdx.x;
    const int w    = tid >> 5;
    const int lane = tid & 31;

    const int astart = (bid * NATOMS) / NBLK;
    const int aend   = ((bid + 1) * NATOMS) / NBLK;
    const int acnt   = aend - astart;          // 41 or 42

    // ---- TMA prologue: kick 3 bulk copies, then do mu while they fly -------
    const uint32_t mb   = (uint32_t)__cvta_generic_to_shared(mbar);
    const uint32_t sH0u = (uint32_t)__cvta_generic_to_shared(sH0);
    const uint32_t sWqu = (uint32_t)__cvta_generic_to_shared(sWq);
    const uint32_t sWcu = (uint32_t)__cvta_generic_to_shared(sWc);
    const uint32_t h0_bytes = (uint32_t)acnt * FDIM * 4u;

    if (tid == 0)
        asm volatile("mbarrier.init.shared.b64 [%0], 1;" :: "r"(mb) : "memory");
    __syncthreads();
    if (tid == 0) {
        const uint32_t total = 2u * FDIM * HDIM * 4u + h0_bytes;
        asm volatile("mbarrier.arrive.expect_tx.shared.b64 _, [%0], %1;"
                     :: "r"(mb), "r"(total) : "memory");
        tma_bulk_1d(sWqu, qW1, FDIM * HDIM * 4u, mb);
        tma_bulk_1d(sWcu, cW1, FDIM * HDIM * 4u, mb);
        tma_bulk_1d(sH0u, h0 + (size_t)astart * FDIM, h0_bytes, mb);
    }

    // ---- mu = h1 @ muW : ALL 32 warps, 1-2 atoms each (overlaps TMA) -------
    {
        const float4 mw4 = *reinterpret_cast<const float4*>(muW + lane * 4);
        const int loc0 = w;
        const int loc1 = w + 32;
        const bool has2 = (loc1 < acnt);
        if (loc0 < acnt) {
            const float* hr0 = h1 + (size_t)(astart + loc0) * 3 * FDIM;
            const float* hr1 = h1 + (size_t)(astart + (has2 ? loc1 : loc0)) * 3 * FDIM;
            float m0[3], m1[3];
            #pragma unroll
            for (int d = 0; d < 3; d++) {
                const float4 a = *reinterpret_cast<const float4*>(hr0 + d * FDIM + lane * 4);
                const float4 b = *reinterpret_cast<const float4*>(hr1 + d * FDIM + lane * 4);
                m0[d] = a.x * mw4.x + a.y * mw4.y + a.z * mw4.z + a.w * mw4.w;
                m1[d] = b.x * mw4.x + b.y * mw4.y + b.z * mw4.z + b.w * mw4.w;
            }
            #pragma unroll
            for (int o = 16; o > 0; o >>= 1) {
                #pragma unroll
                for (int d = 0; d < 3; d++) {
                    m0[d] += __shfl_down_sync(0xffffffffu, m0[d], o);
                    m1[d] += __shfl_down_sync(0xffffffffu, m1[d], o);
                }
            }
            if (lane == 0) {
                s_mu[loc0][0] = m0[0]; s_mu[loc0][1] = m0[1]; s_mu[loc0][2] = m0[2];
                if (has2) { s_mu[loc1][0] = m1[0]; s_mu[loc1][1] = m1[1]; s_mu[loc1][2] = m1[2]; }
            }
        }
    }

    // ---- wait for TMA, transform h0 -> pair-major f32x2 --------------------
    asm volatile(
        "{\n\t.reg .pred P;\n"
        "WAIT_%=:\n\t"
        "mbarrier.try_wait.parity.acquire.cta.shared::cta.b64 P, [%0], 0, 0x989680;\n\t"
        "@!P bra WAIT_%=;\n\t}"
        :: "r"(mb) : "memory");

    // word index for (atom a, feature f): (a>>1)*256 + f*2 + (a&1)
    for (int idx = tid; idx < ASLOT * FDIM; idx += NTHR) {
        const int a = idx >> 7, f = idx & 127;
        const float v = (a < acnt) ? sH0[a * FDIM + f] : 0.0f;
        sH0P[(a >> 1) * 256 + f * 2 + (a & 1)] = v;
    }
    __syncthreads();

    // ---- MLPs: 32 warps = 2 sections x 4 atom-groups x 2 unit-halves x 2 f-halves
    const int sec = w >> 4;                    // 0 = q, 1 = c6
    const int wl  = w & 15;
    const int g   = wl >> 2;                   // atom group (12 atoms)
    const int uh  = (wl >> 1) & 1;             // unit half (32 units)
    const int fh  = wl & 1;                    // feature half (64 features)
    const int t   = uh * 32 + lane;
    const float* sW = sec ? sWc : sWq;
    const float* B1 = sec ? cb1 : qb1;
    const float* W2 = sec ? cW2 : qW2;

    long long acc[6] = {0, 0, 0, 0, 0, 0};
    const int pb = g * 6;

    #pragma unroll 2
    for (int f4 = fh * 16; f4 < fh * 16 + 16; f4++) {
        const float w0 = sW[(4 * f4 + 0) * HDIM + t];
        const float w1 = sW[(4 * f4 + 1) * HDIM + t];
        const float w2 = sW[(4 * f4 + 2) * HDIM + t];
        const float w3 = sW[(4 * f4 + 3) * HDIM + t];
        const long long d0 = dupf(w0), d1 = dupf(w1);
        const long long d2 = dupf(w2), d3 = dupf(w3);
        #pragma unroll
        for (int p = 0; p < 6; p++) {
            const double2* hp = reinterpret_cast<const double2*>(
                &sH0P[(pb + p) * 256 + f4 * 8]);
            const double2 hA = hp[0];
            const double2 hB = hp[1];
            ffma2(acc[p], __double_as_longlong(hA.x), d0);
            ffma2(acc[p], __double_as_longlong(hA.y), d1);
            ffma2(acc[p], __double_as_longlong(hB.x), d2);
            ffma2(acc[p], __double_as_longlong(hB.y), d3);
        }
    }

    // ---- combine f-halves through smem (overlay on dead sH0) ---------------
    // index: (((sec*4+g)*2+uh)*6+p)*32 + lane
    const int cbase = (((sec * 4 + g) * 2 + uh) * 6) * 32 + lane;
    __syncthreads();                           // sH0 raw reads are done
    if (fh == 0) {
        #pragma unroll
        for (int p = 0; p < 6; p++) sComb[cbase + p * 32] = acc[p];
    }
    __syncthreads();
    if (fh == 1) {
        const float bias1 = B1[t];
        const float w2c   = W2[t];
        float v[12];
        #pragma unroll
        for (int p = 0; p < 6; p++) {
            float a0, a1, b0, b1v;
            unpack2(acc[p], a0, a1);
            unpack2(sComb[cbase + p * 32], b0, b1v);
            const float x0 = a0 + b0 + bias1;
            const float x1 = a1 + b1v + bias1;
            v[2 * p]     = x0 * __fdividef(1.0f, 1.0f + __expf(-x0)) * w2c;
            v[2 * p + 1] = x1 * __fdividef(1.0f, 1.0f + __expf(-x1)) * w2c;
        }
        #pragma unroll
        for (int k = 0; k < 12; k++) {
            #pragma unroll
            for (int o = 16; o > 0; o >>= 1)
                v[k] += __shfl_down_sync(0xffffffffu, v[k], o);
        }
        if (lane == 0) {
            float (*dst)[2][12] = sec ? sPC : sPQ;
            #pragma unroll
            for (int k = 0; k < 12; k++) dst[g][uh][k] = v[k];
        }
    }
    __syncthreads();

    // ---- Pack per-atom data + segment boundaries ---------------------------
    if (tid < acnt) {
        const int grp = tid / 12, idx = tid % 12;
        const float qv  = sPQ[grp][0][idx] + sPQ[grp][1][idx] + qb2[0];
        const float cv  = sPC[grp][0][idx] + sPC[grp][1][idx] + cb2[0];
        const float sp  = fmaxf(cv, 0.0f) + log1pf(__expf(-fabsf(cv)));
        const int i = astart + tid;
        g_A[i] = make_float4(pos[3 * i], pos[3 * i + 1], pos[3 * i + 2], qv);
        g_B[i] = make_float4(s_mu[tid][0], s_mu[tid][1], s_mu[tid][2], sqrtf(sp));
        const int b = batch[i];
        if (i == 0 || batch[i - 1] != b) g_segs[b] = i;
        if (i == NATOMS - 1 || batch[i + 1] != b) g_sege[b] = i + 1;
    }

    grid_barrier();

    // ---- Per-molecule mean charge ------------------------------------------
    for (int m = w; m < NMOL; m += NWARP) {
        const int s0 = g_segs[m], e0 = g_sege[m];
        float qs = 0.0f;
        for (int k = s0 + lane; k < e0; k += 32) qs += g_A[k].w;
        #pragma unroll
        for (int o = 16; o > 0; o >>= 1)
            qs += __shfl_xor_sync(0xffffffffu, qs, o);
        if (lane == 0) s_qmean[m] = (e0 > s0) ? qs / (float)(e0 - s0) : 0.0f;
    }
    __syncthreads();

    // ---- Pairwise energy: each warp one mirrored (i, N-1-i) pair -----------
    double acc2 = 0.0;
    const int gw = bid * NWARP + w;
    if (gw < NATOMS / 2) {
        #pragma unroll
        for (int m = 0; m < 2; m++) {
            const int i  = m ? (NATOMS - 1 - gw) : gw;
            const int b  = batch[i];
            const int e0 = g_sege[b];
            const float qm = s_qmean[b];

            const float4 Ai = g_A[i];
            const float4 Bi = g_B[i];
            const float qi = Ai.w - qm;

            float facc = 0.0f;
            for (int j = i + 1 + lane; j < e0; j += 32) {
                const float4 Aj = g_A[j];
                const float4 Bj = g_B[j];
                const float dx = Ai.x - Aj.x;
                const float dy = Ai.y - Aj.y;
                const float dz = Ai.z - Aj.z;
                const float d2r  = dx * dx + dy * dy + dz * dz;
                const float d2   = d2r + 1e-8f;
                const float invd = rsqrtf(d2);
                const float dist = d2 * invd;

                const float qj    = Aj.w - qm;
                const float taper = 1.0f - __expf(-0.5f * dist);
                const float ec    = qi * qj * invd * taper * 14.399f;

                const float r6    = d2r * d2r * d2r;
                const float aden  = r6 + 20.0f;
                const float bden  = d2r * dist + 10.0f;
                const float invab = __fdividef(1.0f, aden * bden);

                const float ev = -Bi.w * Bj.w * (invab * bden);

                const float mumu = Bi.x * Bj.x + Bi.y * Bj.y + Bi.z * Bj.z;
                const float di   = (Bi.x * dx + Bi.y * dy + Bi.z * dz) * invd;
                const float dj   = (Bj.x * dx + Bj.y * dy + Bj.z * dz) * invd;
                const float ed   = (mumu - 3.0f * di * dj) * (invab * aden);

                facc += ec + ev + ed;
            }
            acc2 += (double)facc;
        }
    }

    #pragma unroll
    for (int o = 16; o > 0; o >>= 1)
        acc2 += __shfl_down_sync(0xffffffffu, acc2, o);
    if (lane == 0) sDD[w] = acc2;
    __syncthreads();
    if (tid == 0) {
        double ts = 0.0;
        #pragma unroll
        for (int k = 0; k < NWARP; k++) ts += sDD[k];
        g_partial[bid] = ts;
        __threadfence();
        s_last = (atomicAdd(&g_done, 1) == NBLK - 1) ? 1 : 0;
    }
    __syncthreads();

    // ---- Last-arriving block reduces 148 partials and writes output --------
    if (s_last) {
        __threadfence();
        if (tid == 0) g_done = 0;
        double v = (tid < NBLK) ? g_partial[tid] : 0.0;
        #pragma unroll
        for (int o = 16; o > 0; o >>= 1)
            v += __shfl_down_sync(0xffffffffu, v, o);
        if (lane == 0 && w < 5) sDD[w] = v;
        __syncthreads();
        if (tid == 0) {
            double tot = 0.0;
            #pragma unroll
            for (int k = 0; k < 5; k++) tot += sDD[k];
            out[0] = (float)tot;               // LONG_RANGE_SCALE = 1.0
        }
    }
}

// ---------------------------------------------------------------------------
extern "C" void kernel_launch(void* const* d_in, const int* in_sizes, int n_in,
                              void* d_out, int out_size) {
    const float* h0    = (const float*)d_in[0];
    const float* h1    = (const float*)d_in[1];
    const float* pos   = (const float*)d_in[2];
    const int*   batch = (const int*)  d_in[3];
    const float* qW1   = (const float*)d_in[4];
    const float* qb1   = (const float*)d_in[5];
    const float* qW2   = (const float*)d_in[6];
    const float* qb2   = (const float*)d_in[7];
    const float* cW1   = (const float*)d_in[8];
    const float* cb1   = (const float*)d_in[9];
    const float* cW2   = (const float*)d_in[10];
    const float* cb2   = (const float*)d_in[11];
    const float* muW   = (const float*)d_in[12];

    const int smem_bytes = (ASLOT * FDIM + 2 * FDIM * HDIM + ASLOT * FDIM)
                           * (int)sizeof(float);   // 112 KB
    cudaFuncSetAttribute(fused_kernel,
                         cudaFuncAttributeMaxDynamicSharedMemorySize, smem_bytes);
    fused_kernel<<<NBLK, NTHR, smem_bytes>>>(
        h0, h1, pos, batch,
        qW1, qb1, qW2, qb2,
        cW1, cb1, cW2, cb2,
        muW, (float*)d_out);
}

// round 9
// speedup vs baseline: 1.1616x; 1.1616x over previous
#include <cuda_runtime.h>
#include <cstdint>

#define NATOMS 6144
#define FDIM   128
#define HDIM   64
#define NMOL   48
#define NBLK   148     // co-resident on B300(148)/GB300(152)
#define NTHR   768
#define NWARP  24
#define NWTOT  (NBLK * NWARP)
#define ASLOT  48      // padded atom slots per block (acnt is 41..42)

// Device-global scratch. Deterministic overwrites; g_qsumF is zero at load and
// re-zeroed by the last-arriving block each replay (after all reads).
__device__ float4 g_A[NATOMS];        // pos.xyz, q_raw
__device__ float4 g_B[NATOMS];        // mu.xyz, sqrt(softplus(c6))
__device__ int    g_segs[NMOL];
__device__ int    g_sege[NMOL];
__device__ float  g_qsumF[NMOL];      // per-molecule q sums (atomic, replay-safe)
__device__ double g_partial[NBLK];
__device__ volatile int g_sense;
__device__ int    g_count;
__device__ int    g_done;

__device__ __forceinline__ void grid_barrier() {
    __syncthreads();
    if (threadIdx.x == 0) {
        int s = g_sense;
        __threadfence();
        if (atomicAdd(&g_count, 1) == NBLK - 1) {
            g_count = 0;
            __threadfence();
            g_sense = s ^ 1;
        } else {
            while (g_sense == s) { }
        }
    }
    __syncthreads();
    __threadfence();
}

// ---- f32x2 packed-FMA helpers (FFMA2 on sm_100+) ---------------------------
__device__ __forceinline__ long long dupf(float w) {
    long long d; unsigned r = __float_as_uint(w);
    asm("mov.b64 %0, {%1, %1};" : "=l"(d) : "r"(r));
    return d;
}
__device__ __forceinline__ void ffma2(long long& a, long long h, long long w) {
    asm("fma.rn.f32x2 %0, %1, %2, %0;" : "+l"(a) : "l"(h), "l"(w));
}
__device__ __forceinline__ void unpack2(long long a, float& lo, float& hi) {
    unsigned l, h;
    asm("mov.b64 {%0, %1}, %2;" : "=r"(l), "=r"(h) : "l"(a));
    lo = __uint_as_float(l); hi = __uint_as_float(h);
}

__device__ __forceinline__ void tma_bulk_1d(uint32_t dst, const void* src,
                                            uint32_t bytes, uint32_t mbar) {
    asm volatile(
        "cp.async.bulk.shared::cta.global.mbarrier::complete_tx::bytes [%0], [%1], %2, [%3];"
        :: "r"(dst), "l"(src), "r"(bytes), "r"(mbar) : "memory");
}
__device__ __forceinline__ void mbar_wait0(uint32_t mb) {
    asm volatile(
        "{\n\t.reg .pred P;\n"
        "WAIT_%=:\n\t"
        "mbarrier.try_wait.parity.acquire.cta.shared::cta.b64 P, [%0], 0, 0x989680;\n\t"
        "@!P bra WAIT_%=;\n\t}"
        :: "r"(mb) : "memory");
}

extern "C" __global__ void __launch_bounds__(NTHR, 1) fused_kernel(
    const float* __restrict__ h0, const float* __restrict__ h1,
    const float* __restrict__ pos, const int* __restrict__ batch,
    const float* __restrict__ qW1, const float* __restrict__ qb1,
    const float* __restrict__ qW2, const float* __restrict__ qb2,
    const float* __restrict__ cW1, const float* __restrict__ cb1,
    const float* __restrict__ cW2, const float* __restrict__ cb2,
    const float* __restrict__ muW, float* __restrict__ out)
{
    extern __shared__ float smem[];
    float* sH0  = smem;                        // 48*128 = 24 KB (TMA dst; overlaid later)
    float* sWq  = smem + ASLOT * FDIM;         // 32 KB (TMA dst)
    float* sWc  = sWq + FDIM * HDIM;           // 32 KB (TMA dst)
    float* sH0P = sWc + FDIM * HDIM;           // 24 KB pair-major acts
    long long* sComb = (long long*)sH0;        // overlay: 8 slots * 32 lanes * 12 = 24 KB

    __shared__ float  sPQ[4][12];              // q per-atom results (pre-b2)
    __shared__ float  sPC[4][12];              // c6 per-atom results (pre-b2)
    __shared__ float  s_mu[ASLOT][3];
    __shared__ float  s_qp[NMOL];              // block-local molecule partial q sums
    __shared__ float  s_qmean[NMOL];
    __shared__ double sDD[NWARP];
    __shared__ int    s_last;
    __shared__ __align__(8) unsigned long long mbar[1];

    const int tid  = threadIdx.x;
    const int bid  = blockIdx.x;
    const int w    = tid >> 5;
    const int lane = tid & 31;

    const int astart = (bid * NATOMS) / NBLK;
    const int aend   = ((bid + 1) * NATOMS) / NBLK;
    const int acnt   = aend - astart;          // 41 or 42

    const uint32_t mb   = (uint32_t)__cvta_generic_to_shared(mbar);
    const uint32_t sH0u = (uint32_t)__cvta_generic_to_shared(sH0);
    const uint32_t sWqu = (uint32_t)__cvta_generic_to_shared(sWq);
    const uint32_t sWcu = (uint32_t)__cvta_generic_to_shared(sWc);

    if (tid == 0)
        asm volatile("mbarrier.init.shared.b64 [%0], 1;" :: "r"(mb) : "memory");
    if (tid < NMOL) s_qp[tid] = 0.0f;
    __syncthreads();

    // ========== Warp-specialized phase 1 ====================================
    if (w < 16) {
        // ---- TMA prologue (MLP warps only; mu warps bypass) ----------------
        const uint32_t h0_bytes = (uint32_t)acnt * FDIM * 4u;
        if (tid == 0) {
            const uint32_t total = 2u * FDIM * HDIM * 4u + h0_bytes;
            asm volatile("mbarrier.arrive.expect_tx.shared.b64 _, [%0], %1;"
                         :: "r"(mb), "r"(total) : "memory");
            tma_bulk_1d(sWqu, qW1, FDIM * HDIM * 4u, mb);
            tma_bulk_1d(sWcu, cW1, FDIM * HDIM * 4u, mb);
            tma_bulk_1d(sH0u, h0 + (size_t)astart * FDIM, h0_bytes, mb);
        }
        mbar_wait0(mb);

        // ---- transform h0 -> pair-major f32x2 layout (512 threads) ---------
        // word index for (atom a, feature f): (a>>1)*256 + f*2 + (a&1)
        for (int idx = tid; idx < ASLOT * FDIM; idx += 512) {
            const int a = idx >> 7, f = idx & 127;
            const float v = (a < acnt) ? sH0[a * FDIM + f] : 0.0f;
            sH0P[(a >> 1) * 256 + f * 2 + (a & 1)] = v;
        }
        asm volatile("bar.sync 1, 512;" ::: "memory");

        // ---- MLPs: 16 warps = 2 MLPs x 4 pair-groups x 2 f-halves ----------
        // Each lane owns units {2*lane, 2*lane+1}; 6 atom-pairs per warp.
        const int sec = w >> 3;                // 0 = q, 1 = c6
        const int wl  = w & 7;
        const int pg  = wl >> 1;               // pair-group (6 pairs = 12 atoms)
        const int fh  = wl & 1;                // feature half
        const float* sW = sec ? sWc : sWq;
        const float* B1 = sec ? cb1 : qb1;
        const float* W2 = sec ? cW2 : qW2;

        long long acc[6][2];
        #pragma unroll
        for (int p = 0; p < 6; p++) { acc[p][0] = 0; acc[p][1] = 0; }
        const int pb = pg * 6;

        #pragma unroll 2
        for (int f4 = fh * 16; f4 < fh * 16 + 16; f4++) {
            float2 wv[4];
            #pragma unroll
            for (int k = 0; k < 4; k++)
                wv[k] = *reinterpret_cast<const float2*>(
                    &sW[(4 * f4 + k) * HDIM + 2 * lane]);
            const long long u0w0 = dupf(wv[0].x), u1w0 = dupf(wv[0].y);
            const long long u0w1 = dupf(wv[1].x), u1w1 = dupf(wv[1].y);
            const long long u0w2 = dupf(wv[2].x), u1w2 = dupf(wv[2].y);
            const long long u0w3 = dupf(wv[3].x), u1w3 = dupf(wv[3].y);
            #pragma unroll
            for (int p = 0; p < 6; p++) {
                const double2* hp = reinterpret_cast<const double2*>(
                    &sH0P[(pb + p) * 256 + f4 * 8]);
                const double2 hA = hp[0];      // feats 4f4, 4f4+1 (atom-pair packed)
                const double2 hB = hp[1];      // feats 4f4+2, 4f4+3
                const long long a0 = __double_as_longlong(hA.x);
                const long long a1 = __double_as_longlong(hA.y);
                const long long a2 = __double_as_longlong(hB.x);
                const long long a3 = __double_as_longlong(hB.y);
                ffma2(acc[p][0], a0, u0w0); ffma2(acc[p][1], a0, u1w0);
                ffma2(acc[p][0], a1, u0w1); ffma2(acc[p][1], a1, u1w1);
                ffma2(acc[p][0], a2, u0w2); ffma2(acc[p][1], a2, u1w2);
                ffma2(acc[p][0], a3, u0w3); ffma2(acc[p][1], a3, u1w3);
            }
        }

        // ---- combine f-halves through smem (overlay on dead sH0) -----------
        const int slot = ((sec * 4 + pg) * 32 + lane) * 12;
        asm volatile("bar.sync 1, 512;" ::: "memory");   // sH0 raw reads done
        if (fh == 0) {
            #pragma unroll
            for (int p = 0; p < 6; p++) {
                sComb[slot + 2 * p]     = acc[p][0];
                sComb[slot + 2 * p + 1] = acc[p][1];
            }
        }
        asm volatile("bar.sync 1, 512;" ::: "memory");
        if (fh == 1) {
            const float2 b1v = *reinterpret_cast<const float2*>(&B1[2 * lane]);
            const float2 w2v = *reinterpret_cast<const float2*>(&W2[2 * lane]);
            float v[12];
            #pragma unroll
            for (int p = 0; p < 6; p++) {
                float hA0, hB0, hA1, hB1, oA0, oB0, oA1, oB1;
                unpack2(acc[p][0], hA0, hB0);
                unpack2(acc[p][1], hA1, hB1);
                unpack2(sComb[slot + 2 * p],     oA0, oB0);
                unpack2(sComb[slot + 2 * p + 1], oA1, oB1);
                const float xA0 = hA0 + oA0 + b1v.x;
                const float xB0 = hB0 + oB0 + b1v.x;
                const float xA1 = hA1 + oA1 + b1v.y;
                const float xB1 = hB1 + oB1 + b1v.y;
                const float sA0 = xA0 * __fdividef(1.0f, 1.0f + __expf(-xA0)) * w2v.x;
                const float sB0 = xB0 * __fdividef(1.0f, 1.0f + __expf(-xB0)) * w2v.x;
                const float sA1 = xA1 * __fdividef(1.0f, 1.0f + __expf(-xA1)) * w2v.y;
                const float sB1 = xB1 * __fdividef(1.0f, 1.0f + __expf(-xB1)) * w2v.y;
                v[2 * p]     = sA0 + sA1;      // atom 2(pb+p)
                v[2 * p + 1] = sB0 + sB1;      // atom 2(pb+p)+1
            }
            #pragma unroll
            for (int k = 0; k < 12; k++) {
                #pragma unroll
                for (int o = 16; o > 0; o >>= 1)
                    v[k] += __shfl_down_sync(0xffffffffu, v[k], o);
            }
            if (lane == 0) {
                float (*dst)[12] = sec ? sPC : sPQ;
                #pragma unroll
                for (int k = 0; k < 12; k++) dst[pg][k] = v[k];
            }
        }
    } else {
        // ---- mu warps (16-23): start immediately, h1 from global -----------
        const int mw = w - 16;
        const float4 mw4 = *reinterpret_cast<const float4*>(muW + lane * 4);
        for (int base = mw; base < acnt; base += 16) {
            const int loc1 = base + 8;
            const bool has2 = (loc1 < acnt);
            const float* hr0 = h1 + (size_t)(astart + base) * 3 * FDIM;
            const float* hr1 = h1 + (size_t)(astart + (has2 ? loc1 : base)) * 3 * FDIM;
            float m0[3], m1[3];
            #pragma unroll
            for (int d = 0; d < 3; d++) {
                const float4 a = *reinterpret_cast<const float4*>(hr0 + d * FDIM + lane * 4);
                const float4 b = *reinterpret_cast<const float4*>(hr1 + d * FDIM + lane * 4);
                m0[d] = a.x * mw4.x + a.y * mw4.y + a.z * mw4.z + a.w * mw4.w;
                m1[d] = b.x * mw4.x + b.y * mw4.y + b.z * mw4.z + b.w * mw4.w;
            }
            #pragma unroll
            for (int o = 16; o > 0; o >>= 1) {
                #pragma unroll
                for (int d = 0; d < 3; d++) {
                    m0[d] += __shfl_down_sync(0xffffffffu, m0[d], o);
                    m1[d] += __shfl_down_sync(0xffffffffu, m1[d], o);
                }
            }
            if (lane == 0) {
                s_mu[base][0] = m0[0]; s_mu[base][1] = m0[1]; s_mu[base][2] = m0[2];
                if (has2) { s_mu[loc1][0] = m1[0]; s_mu[loc1][1] = m1[1]; s_mu[loc1][2] = m1[2]; }
            }
        }
    }
    __syncthreads();

    // ---- Pack per-atom data + segment boundaries + molecule q partials -----
    if (tid < acnt) {
        const int grp = tid / 12, idx = tid % 12;
        const float qv  = sPQ[grp][idx] + qb2[0];
        const float cv  = sPC[grp][idx] + cb2[0];
        const float sp  = fmaxf(cv, 0.0f) + log1pf(__expf(-fabsf(cv)));
        const int i = astart + tid;
        const int b = batch[i];
        g_A[i] = make_float4(pos[3 * i], pos[3 * i + 1], pos[3 * i + 2], qv);
        g_B[i] = make_float4(s_mu[tid][0], s_mu[tid][1], s_mu[tid][2], sqrtf(sp));
        if (i == 0 || batch[i - 1] != b) g_segs[b] = i;
        if (i == NATOMS - 1 || batch[i + 1] != b) g_sege[b] = i + 1;
        atomicAdd(&s_qp[b], qv);
    }
    __syncthreads();
    // push nonzero partials (adding 0.0 is a no-op, so the guard is exact)
    if (tid < NMOL && s_qp[tid] != 0.0f) atomicAdd(&g_qsumF[tid], s_qp[tid]);

    grid_barrier();

    // ---- qmean staging: one LDG round (sums already global-complete) -------
    if (tid < NMOL) {
        const int cnt = g_sege[tid] - g_segs[tid];
        s_qmean[tid] = (cnt > 0) ? g_qsumF[tid] / (float)cnt : 0.0f;
    }
    __syncthreads();

    // ---- Pairwise energy (i<j; all three terms symmetric) ------------------
    double acc2 = 0.0;
    for (int i = bid * NWARP + w; i < NATOMS; i += NWTOT) {
        const int b  = batch[i];
        const int e0 = g_sege[b];
        const float qm = s_qmean[b];

        const float4 Ai = g_A[i];
        const float4 Bi = g_B[i];
        const float qi = Ai.w - qm;

        float facc = 0.0f;
        for (int j = i + 1 + lane; j < e0; j += 32) {
            const float4 Aj = g_A[j];
            const float4 Bj = g_B[j];
            const float dx = Ai.x - Aj.x;
            const float dy = Ai.y - Aj.y;
            const float dz = Ai.z - Aj.z;
            const float d2r  = dx * dx + dy * dy + dz * dz;
            const float d2   = d2r + 1e-8f;
            const float invd = rsqrtf(d2);                    // MUFU 1
            const float dist = d2 * invd;

            const float qj    = Aj.w - qm;
            const float taper = 1.0f - __expf(-0.5f * dist);  // MUFU 2
            const float ec    = qi * qj * invd * taper * 14.399f;

            const float r6    = d2r * d2r * d2r;
            const float aden  = r6 + 20.0f;
            const float bden  = d2r * dist + 10.0f;
            const float invab = __fdividef(1.0f, aden * bden); // MUFU 3

            const float ev = -Bi.w * Bj.w * (invab * bden);

            const float mumu = Bi.x * Bj.x + Bi.y * Bj.y + Bi.z * Bj.z;
            const float di   = (Bi.x * dx + Bi.y * dy + Bi.z * dz) * invd;
            const float dj   = (Bj.x * dx + Bj.y * dy + Bj.z * dz) * invd;
            const float ed   = (mumu - 3.0f * di * dj) * (invab * aden);

            facc += ec + ev + ed;
        }
        acc2 += (double)facc;
    }

    #pragma unroll
    for (int o = 16; o > 0; o >>= 1)
        acc2 += __shfl_down_sync(0xffffffffu, acc2, o);
    if (lane == 0) sDD[w] = acc2;
    __syncthreads();
    if (tid == 0) {
        double ts = 0.0;
        #pragma unroll
        for (int k = 0; k < NWARP; k++) ts += sDD[k];
        g_partial[bid] = ts;
        __threadfence();
        s_last = (atomicAdd(&g_done, 1) == NBLK - 1) ? 1 : 0;
    }
    __syncthreads();

    // ---- Last-arriving block: zero qsum for next replay, reduce, write -----
    if (s_last) {
        __threadfence();
        if (tid == 0) g_done = 0;
        if (tid < NMOL) g_qsumF[tid] = 0.0f;   // all readers finished (ticket)
        double v = (tid < NBLK) ? g_partial[tid] : 0.0;
        #pragma unroll
        for (int o = 16; o > 0; o >>= 1)
            v += __shfl_down_sync(0xffffffffu, v, o);
        if (lane == 0 && w < 5) sDD[w] = v;
        __syncthreads();
        if (tid == 0) {
            double tot = 0.0;
            #pragma unroll
            for (int k = 0; k < 5; k++) tot += sDD[k];
            out[0] = (float)tot;               // LONG_RANGE_SCALE = 1.0
        }
    }
}

// ---------------------------------------------------------------------------
extern "C" void kernel_launch(void* const* d_in, const int* in_sizes, int n_in,
                              void* d_out, int out_size) {
    const float* h0    = (const float*)d_in[0];
    const float* h1    = (const float*)d_in[1];
    const float* pos   = (const float*)d_in[2];
    const int*   batch = (const int*)  d_in[3];
    const float* qW1   = (const float*)d_in[4];
    const float* qb1   = (const float*)d_in[5];
    const float* qW2   = (const float*)d_in[6];
    const float* qb2   = (const float*)d_in[7];
    const float* cW1   = (const float*)d_in[8];
    const float* cb1   = (const float*)d_in[9];
    const float* cW2   = (const float*)d_in[10];
    const float* cb2   = (const float*)d_in[11];
    const float* muW   = (const float*)d_in[12];

    const int smem_bytes = (ASLOT * FDIM + 2 * FDIM * HDIM + ASLOT * FDIM)
                           * (int)sizeof(float);   // 112 KB
    cudaFuncSetAttribute(fused_kernel,
                         cudaFuncAttributeMaxDynamicSharedMemorySize, smem_bytes);
    fused_kernel<<<NBLK, NTHR, smem_bytes>>>(
        h0, h1, pos, batch,
        qW1, qb1, qW2, qb2,
        cW1, cb1, cW2, cb2,
        muW, (float*)d_out);
}

// round 10
// speedup vs baseline: 1.2453x; 1.0721x over previous
#include <cuda_runtime.h>
#include <cstdint>

#define NATOMS 6144
#define FDIM   128
#define HDIM   64
#define NMOL   48
#define NBLK   148     // co-resident on B300(148)/GB300(152)
#define NTHR   768
#define NWARP  24
#define NWTOT  (NBLK * NWARP)
#define ASLOT  42      // exact atom slots (acnt is 41..42)
#define NPAIRS 21      // ASLOT/2
#define SH0CAP 48      // TMA landing buffer rows (>= acnt)

// Device-global scratch. Deterministic overwrites; g_qsumF is zero at load and
// re-zeroed by the last-arriving block each replay (after all reads).
__device__ float4 g_A[NATOMS];        // pos.xyz, q_raw
__device__ float4 g_B[NATOMS];        // mu.xyz, sqrt(softplus(c6))
__device__ int    g_segs[NMOL];
__device__ int    g_sege[NMOL];
__device__ float  g_qsumF[NMOL];      // per-molecule q sums (atomic, replay-safe)
__device__ double g_partial[NBLK];
__device__ volatile int g_sense;
__device__ int    g_count;
__device__ int    g_done;

__device__ __forceinline__ void grid_barrier() {
    __syncthreads();
    if (threadIdx.x == 0) {
        int s = g_sense;
        __threadfence();
        if (atomicAdd(&g_count, 1) == NBLK - 1) {
            g_count = 0;
            __threadfence();
            g_sense = s ^ 1;
        } else {
            while (g_sense == s) { }
        }
    }
    __syncthreads();
    __threadfence();
}

// ---- f32x2 packed-FMA helpers (FFMA2 on sm_100+) ---------------------------
__device__ __forceinline__ long long dupf(float w) {
    long long d; unsigned r = __float_as_uint(w);
    asm("mov.b64 %0, {%1, %1};" : "=l"(d) : "r"(r));
    return d;
}
__device__ __forceinline__ void ffma2(long long& a, long long h, long long w) {
    asm("fma.rn.f32x2 %0, %1, %2, %0;" : "+l"(a) : "l"(h), "l"(w));
}
__device__ __forceinline__ void unpack2(long long a, float& lo, float& hi) {
    unsigned l, h;
    asm("mov.b64 {%0, %1}, %2;" : "=r"(l), "=r"(h) : "l"(a));
    lo = __uint_as_float(l); hi = __uint_as_float(h);
}

__device__ __forceinline__ void tma_bulk_1d(uint32_t dst, const void* src,
                                            uint32_t bytes, uint32_t mbar) {
    asm volatile(
        "cp.async.bulk.shared::cta.global.mbarrier::complete_tx::bytes [%0], [%1], %2, [%3];"
        :: "r"(dst), "l"(src), "r"(bytes), "r"(mbar) : "memory");
}
__device__ __forceinline__ void mbar_wait0(uint32_t mb) {
    asm volatile(
        "{\n\t.reg .pred P;\n"
        "WAIT_%=:\n\t"
        "mbarrier.try_wait.parity.acquire.cta.shared::cta.b64 P, [%0], 0, 0x989680;\n\t"
        "@!P bra WAIT_%=;\n\t}"
        :: "r"(mb) : "memory");
}

extern "C" __global__ void __launch_bounds__(NTHR, 1) fused_kernel(
    const float* __restrict__ h0, const float* __restrict__ h1,
    const float* __restrict__ pos, const int* __restrict__ batch,
    const float* __restrict__ qW1, const float* __restrict__ qb1,
    const float* __restrict__ qW2, const float* __restrict__ qb2,
    const float* __restrict__ cW1, const float* __restrict__ cb1,
    const float* __restrict__ cW2, const float* __restrict__ cb2,
    const float* __restrict__ muW, float* __restrict__ out)
{
    extern __shared__ float smem[];
    float* sH0  = smem;                        // 48*128 = 24 KB (TMA dst; overlaid later)
    float* sWq  = smem + SH0CAP * FDIM;        // 32 KB (TMA dst)
    float* sWc  = sWq + FDIM * HDIM;           // 32 KB (TMA dst)
    float* sH0P = sWc + FDIM * HDIM;           // 21 pairs x 256 floats = 21 KB
    long long* sComb = (long long*)sH0;        // overlay: 6 grp-slots * 32 * 14 ll = 21 KB

    __shared__ float  sPQ[3][14];              // q per-atom results (pre-b2)
    __shared__ float  sPC[3][14];              // c6 per-atom results (pre-b2)
    __shared__ float  s_mu[ASLOT][3];
    __shared__ float  s_qp[NMOL];              // block-local molecule partial q sums
    __shared__ float  s_qmean[NMOL];
    __shared__ double sDD[NWARP];
    __shared__ int    s_last;
    __shared__ __align__(8) unsigned long long mbar[1];

    const int tid  = threadIdx.x;
    const int bid  = blockIdx.x;
    const int w    = tid >> 5;
    const int lane = tid & 31;

    const int astart = (bid * NATOMS) / NBLK;
    const int aend   = ((bid + 1) * NATOMS) / NBLK;
    const int acnt   = aend - astart;          // 41 or 42

    const uint32_t mb   = (uint32_t)__cvta_generic_to_shared(mbar);
    const uint32_t sH0u = (uint32_t)__cvta_generic_to_shared(sH0);
    const uint32_t sWqu = (uint32_t)__cvta_generic_to_shared(sWq);
    const uint32_t sWcu = (uint32_t)__cvta_generic_to_shared(sWc);

    if (tid == 0)
        asm volatile("mbarrier.init.shared.b64 [%0], 1;" :: "r"(mb) : "memory");
    if (tid < NMOL) s_qp[tid] = 0.0f;
    __syncthreads();

    // ========== Warp-specialized phase 1 ====================================
    if (w < 12) {
        // ---- TMA prologue (MLP warps only; mu warps bypass) ----------------
        const uint32_t h0_bytes = (uint32_t)acnt * FDIM * 4u;
        if (tid == 0) {
            const uint32_t total = 2u * FDIM * HDIM * 4u + h0_bytes;
            asm volatile("mbarrier.arrive.expect_tx.shared.b64 _, [%0], %1;"
                         :: "r"(mb), "r"(total) : "memory");
            tma_bulk_1d(sWqu, qW1, FDIM * HDIM * 4u, mb);
            tma_bulk_1d(sWcu, cW1, FDIM * HDIM * 4u, mb);
            tma_bulk_1d(sH0u, h0 + (size_t)astart * FDIM, h0_bytes, mb);
        }
        mbar_wait0(mb);

        // ---- transform h0 -> pair-major f32x2 layout (384 threads) ---------
        // word index for (atom a, feature f): (a>>1)*256 + f*2 + (a&1)
        for (int idx = tid; idx < ASLOT * FDIM; idx += 384) {
            const int a = idx >> 7, f = idx & 127;
            const float v = (a < acnt) ? sH0[a * FDIM + f] : 0.0f;
            sH0P[(a >> 1) * 256 + f * 2 + (a & 1)] = v;
        }
        asm volatile("bar.sync 1, 384;" ::: "memory");

        // ---- MLPs: 12 warps = 2 MLPs x 3 pair-groups x 2 f-halves ----------
        // Each lane owns units {2*lane, 2*lane+1}; 7 atom-pairs per warp.
        const int sec = w / 6;                 // 0 = q, 1 = c6
        const int wl  = w % 6;
        const int pg  = wl >> 1;               // pair-group (7 pairs = 14 atoms)
        const int fh  = wl & 1;                // feature half
        const float* sW = sec ? sWc : sWq;
        const float* B1 = sec ? cb1 : qb1;
        const float* W2 = sec ? cW2 : qW2;

        long long acc[7][2];
        #pragma unroll
        for (int p = 0; p < 7; p++) { acc[p][0] = 0; acc[p][1] = 0; }
        const int pb = pg * 7;

        #pragma unroll 2
        for (int f4 = fh * 16; f4 < fh * 16 + 16; f4++) {
            float2 wv[4];
            #pragma unroll
            for (int k = 0; k < 4; k++)
                wv[k] = *reinterpret_cast<const float2*>(
                    &sW[(4 * f4 + k) * HDIM + 2 * lane]);
            const long long u0w0 = dupf(wv[0].x), u1w0 = dupf(wv[0].y);
            const long long u0w1 = dupf(wv[1].x), u1w1 = dupf(wv[1].y);
            const long long u0w2 = dupf(wv[2].x), u1w2 = dupf(wv[2].y);
            const long long u0w3 = dupf(wv[3].x), u1w3 = dupf(wv[3].y);
            #pragma unroll
            for (int p = 0; p < 7; p++) {
                const double2* hp = reinterpret_cast<const double2*>(
                    &sH0P[(pb + p) * 256 + f4 * 8]);
                const double2 hA = hp[0];      // feats 4f4, 4f4+1 (atom-pair packed)
                const double2 hB = hp[1];      // feats 4f4+2, 4f4+3
                const long long a0 = __double_as_longlong(hA.x);
                const long long a1 = __double_as_longlong(hA.y);
                const long long a2 = __double_as_longlong(hB.x);
                const long long a3 = __double_as_longlong(hB.y);
                ffma2(acc[p][0], a0, u0w0); ffma2(acc[p][1], a0, u1w0);
                ffma2(acc[p][0], a1, u0w1); ffma2(acc[p][1], a1, u1w1);
                ffma2(acc[p][0], a2, u0w2); ffma2(acc[p][1], a2, u1w2);
                ffma2(acc[p][0], a3, u0w3); ffma2(acc[p][1], a3, u1w3);
            }
        }

        // ---- combine f-halves through smem (overlay on dead sH0) -----------
        const int slot = ((sec * 3 + pg) * 32 + lane) * 14;
        asm volatile("bar.sync 1, 384;" ::: "memory");   // sH0 raw reads done
        if (fh == 0) {
            #pragma unroll
            for (int p = 0; p < 7; p++) {
                sComb[slot + 2 * p]     = acc[p][0];
                sComb[slot + 2 * p + 1] = acc[p][1];
            }
        }
        asm volatile("bar.sync 1, 384;" ::: "memory");
        if (fh == 1) {
            const float2 b1v = *reinterpret_cast<const float2*>(&B1[2 * lane]);
            const float2 w2v = *reinterpret_cast<const float2*>(&W2[2 * lane]);
            float v[14];
            #pragma unroll
            for (int p = 0; p < 7; p++) {
                float hA0, hB0, hA1, hB1, oA0, oB0, oA1, oB1;
                unpack2(acc[p][0], hA0, hB0);
                unpack2(acc[p][1], hA1, hB1);
                unpack2(sComb[slot + 2 * p],     oA0, oB0);
                unpack2(sComb[slot + 2 * p + 1], oA1, oB1);
                const float xA0 = hA0 + oA0 + b1v.x;
                const float xB0 = hB0 + oB0 + b1v.x;
                const float xA1 = hA1 + oA1 + b1v.y;
                const float xB1 = hB1 + oB1 + b1v.y;
                const float sA0 = xA0 * __fdividef(1.0f, 1.0f + __expf(-xA0)) * w2v.x;
                const float sB0 = xB0 * __fdividef(1.0f, 1.0f + __expf(-xB0)) * w2v.x;
                const float sA1 = xA1 * __fdividef(1.0f, 1.0f + __expf(-xA1)) * w2v.y;
                const float sB1 = xB1 * __fdividef(1.0f, 1.0f + __expf(-xB1)) * w2v.y;
                v[2 * p]     = sA0 + sA1;      // atom 2(pb+p)
                v[2 * p + 1] = sB0 + sB1;      // atom 2(pb+p)+1
            }
            #pragma unroll
            for (int k = 0; k < 14; k++) {
                #pragma unroll
                for (int o = 16; o > 0; o >>= 1)
                    v[k] += __shfl_down_sync(0xffffffffu, v[k], o);
            }
            if (lane == 0) {
                float (*dst)[14] = sec ? sPC : sPQ;
                #pragma unroll
                for (int k = 0; k < 14; k++) dst[pg][k] = v[k];
            }
        }
    } else {
        // ---- mu warps (12-23): start immediately, h1 from global -----------
        const float4 mw4 = *reinterpret_cast<const float4*>(muW + lane * 4);
        for (int loc = w - 12; loc < acnt; loc += 12) {
            const float* hr = h1 + (size_t)(astart + loc) * 3 * FDIM;
            float m[3];
            #pragma unroll
            for (int d = 0; d < 3; d++) {
                const float4 a = *reinterpret_cast<const float4*>(hr + d * FDIM + lane * 4);
                m[d] = a.x * mw4.x + a.y * mw4.y + a.z * mw4.z + a.w * mw4.w;
            }
            #pragma unroll
            for (int o = 16; o > 0; o >>= 1) {
                m[0] += __shfl_down_sync(0xffffffffu, m[0], o);
                m[1] += __shfl_down_sync(0xffffffffu, m[1], o);
                m[2] += __shfl_down_sync(0xffffffffu, m[2], o);
            }
            if (lane == 0) { s_mu[loc][0] = m[0]; s_mu[loc][1] = m[1]; s_mu[loc][2] = m[2]; }
        }
    }
    __syncthreads();

    // ---- Pack per-atom data + segment boundaries + molecule q partials -----
    if (tid < acnt) {
        const int grp = tid / 14, idx = tid % 14;
        const float qv  = sPQ[grp][idx] + qb2[0];
        const float cv  = sPC[grp][idx] + cb2[0];
        const float sp  = fmaxf(cv, 0.0f) + log1pf(__expf(-fabsf(cv)));
        const int i = astart + tid;
        const int b = batch[i];
        g_A[i] = make_float4(pos[3 * i], pos[3 * i + 1], pos[3 * i + 2], qv);
        g_B[i] = make_float4(s_mu[tid][0], s_mu[tid][1], s_mu[tid][2], sqrtf(sp));
        if (i == 0 || batch[i - 1] != b) g_segs[b] = i;
        if (i == NATOMS - 1 || batch[i + 1] != b) g_sege[b] = i + 1;
        atomicAdd(&s_qp[b], qv);
    }
    __syncthreads();
    // push nonzero partials (adding 0.0 is a no-op, so the guard is exact)
    if (tid < NMOL && s_qp[tid] != 0.0f) atomicAdd(&g_qsumF[tid], s_qp[tid]);

    grid_barrier();

    // ---- qmean staging: one LDG round (sums already global-complete) -------
    if (tid < NMOL) {
        const int cnt = g_sege[tid] - g_segs[tid];
        s_qmean[tid] = (cnt > 0) ? g_qsumF[tid] / (float)cnt : 0.0f;
    }
    __syncthreads();

    // ---- Pairwise energy (i<j; all terms symmetric), 2-stage pipelined -----
    double acc2 = 0.0;
    for (int i = bid * NWARP + w; i < NATOMS; i += NWTOT) {
        const int b  = batch[i];
        const int e0 = g_sege[b];
        const float qm = s_qmean[b];

        const float4 Ai = g_A[i];
        const float4 Bi = g_B[i];
        const float qi = Ai.w - qm;

        float facc = 0.0f;
        int j = i + 1 + lane;
        if (j < e0) {
            float4 Aj = g_A[j];
            float4 Bj = g_B[j];
            while (true) {
                const int jn = j + 32;
                float4 An, Bn;
                if (jn < e0) { An = g_A[jn]; Bn = g_B[jn]; }   // prefetch

                const float dx = Ai.x - Aj.x;
                const float dy = Ai.y - Aj.y;
                const float dz = Ai.z - Aj.z;
                const float d2r  = dx * dx + dy * dy + dz * dz;
                const float d2   = d2r + 1e-8f;
                const float invd = rsqrtf(d2);                    // MUFU 1
                const float dist = d2 * invd;

                const float qj    = Aj.w - qm;
                const float taper = 1.0f - __expf(-0.5f * dist);  // MUFU 2
                const float ec    = qi * qj * invd * taper * 14.399f;

                const float r6    = d2r * d2r * d2r;
                const float aden  = r6 + 20.0f;
                const float bden  = d2r * dist + 10.0f;
                const float invab = __fdividef(1.0f, aden * bden); // MUFU 3

                const float ev = -Bi.w * Bj.w * (invab * bden);

                const float mumu = Bi.x * Bj.x + Bi.y * Bj.y + Bi.z * Bj.z;
                const float di   = (Bi.x * dx + Bi.y * dy + Bi.z * dz) * invd;
                const float dj   = (Bj.x * dx + Bj.y * dy + Bj.z * dz) * invd;
                const float ed   = (mumu - 3.0f * di * dj) * (invab * aden);

                facc += ec + ev + ed;

                if (jn >= e0) break;
                Aj = An; Bj = Bn; j = jn;
            }
        }
        acc2 += (double)facc;
    }

    #pragma unroll
    for (int o = 16; o > 0; o >>= 1)
        acc2 += __shfl_down_sync(0xffffffffu, acc2, o);
    if (lane == 0) sDD[w] = acc2;
    __syncthreads();
    if (tid == 0) {
        double ts = 0.0;
        #pragma unroll
        for (int k = 0; k < NWARP; k++) ts += sDD[k];
        g_partial[bid] = ts;
        __threadfence();
        s_last = (atomicAdd(&g_done, 1) == NBLK - 1) ? 1 : 0;
    }
    __syncthreads();

    // ---- Last-arriving block: zero qsum for next replay, reduce, write -----
    if (s_last) {
        __threadfence();
        if (tid == 0) g_done = 0;
        if (tid < NMOL) g_qsumF[tid] = 0.0f;   // all readers finished (ticket)
        double v = (tid < NBLK) ? g_partial[tid] : 0.0;
        #pragma unroll
        for (int o = 16; o > 0; o >>= 1)
            v += __shfl_down_sync(0xffffffffu, v, o);
        if (lane == 0 && w < 5) sDD[w] = v;
        __syncthreads();
        if (tid == 0) {
            double tot = 0.0;
            #pragma unroll
            for (int k = 0; k < 5; k++) tot += sDD[k];
            out[0] = (float)tot;               // LONG_RANGE_SCALE = 1.0
        }
    }
}

// ---------------------------------------------------------------------------
extern "C" void kernel_launch(void* const* d_in, const int* in_sizes, int n_in,
                              void* d_out, int out_size) {
    const float* h0    = (const float*)d_in[0];
    const float* h1    = (const float*)d_in[1];
    const float* pos   = (const float*)d_in[2];
    const int*   batch = (const int*)  d_in[3];
    const float* qW1   = (const float*)d_in[4];
    const float* qb1   = (const float*)d_in[5];
    const float* qW2   = (const float*)d_in[6];
    const float* qb2   = (const float*)d_in[7];
    const float* cW1   = (const float*)d_in[8];
    const float* cb1   = (const float*)d_in[9];
    const float* cW2   = (const float*)d_in[10];
    const float* cb2   = (const float*)d_in[11];
    const float* muW   = (const float*)d_in[12];

    const int smem_bytes = (SH0CAP * FDIM + 2 * FDIM * HDIM + NPAIRS * 256)
                           * (int)sizeof(float);   // ~109 KB
    cudaFuncSetAttribute(fused_kernel,
                         cudaFuncAttributeMaxDynamicSharedMemorySize, smem_bytes);
    fused_kernel<<<NBLK, NTHR, smem_bytes>>>(
        h0, h1, pos, batch,
        qW1, qb1, qW2, qb2,
        cW1, cb1, cW2, cb2,
        muW, (float*)d_out);
}